// round 1
// baseline (speedup 1.0000x reference)
#include <cuda_runtime.h>

// Problem dims (fixed by the dataset)
#define Bsz 8
#define Tsz 4096
#define Csz 512
#define Msz (Bsz*Tsz)          // 32768 rows
#define BLsz (Bsz*Csz)         // 4096 scan lanes
#define NCH 32                 // chunks along T
#define LCH (Tsz/NCH)          // 128 steps per chunk
#define NEG_INF -1e38f

// ---- scratch (static device globals; no allocation allowed) ----
__device__ float g_xk[Msz*Csz];
__device__ float g_xv[Msz*Csz];
__device__ float g_xr[Msz*Csz];
__device__ float g_k [Msz*Csz];
__device__ float g_v [Msz*Csz];
__device__ float g_r [Msz*Csz];
__device__ float g_o2[Msz*Csz];
__device__ float g_sp[NCH*BLsz];
__device__ float g_sq[NCH*BLsz];
__device__ float g_so[NCH*BLsz];
__device__ float g_pp[NCH*BLsz];
__device__ float g_pq[NCH*BLsz];
__device__ float g_po[NCH*BLsz];

// =====================================================================
// 1) time-shift + mix: xk/xv/xr = x*mix + shift(x)*(1-mix)   (float4)
// =====================================================================
__global__ void mix_kernel(const float* __restrict__ x,
                           const float* __restrict__ mk,
                           const float* __restrict__ mv,
                           const float* __restrict__ mr) {
    int gid = blockIdx.x * blockDim.x + threadIdx.x;
    int e = gid * 4;
    if (e >= Msz*Csz) return;
    int c = e & (Csz - 1);
    int m = e >> 9;            // /Csz
    int t = m & (Tsz - 1);
    float4 xc = *(const float4*)(x + e);
    float4 xp = make_float4(0.f, 0.f, 0.f, 0.f);
    if (t > 0) xp = *(const float4*)(x + e - Csz);
    float4 k4 = *(const float4*)(mk + c);
    float4 v4 = *(const float4*)(mv + c);
    float4 r4 = *(const float4*)(mr + c);
    float4 ok, ov, orr;
    ok.x = xc.x*k4.x + xp.x*(1.f-k4.x);  ok.y = xc.y*k4.y + xp.y*(1.f-k4.y);
    ok.z = xc.z*k4.z + xp.z*(1.f-k4.z);  ok.w = xc.w*k4.w + xp.w*(1.f-k4.w);
    ov.x = xc.x*v4.x + xp.x*(1.f-v4.x);  ov.y = xc.y*v4.y + xp.y*(1.f-v4.y);
    ov.z = xc.z*v4.z + xp.z*(1.f-v4.z);  ov.w = xc.w*v4.w + xp.w*(1.f-v4.w);
    orr.x = xc.x*r4.x + xp.x*(1.f-r4.x); orr.y = xc.y*r4.y + xp.y*(1.f-r4.y);
    orr.z = xc.z*r4.z + xp.z*(1.f-r4.z); orr.w = xc.w*r4.w + xp.w*(1.f-r4.w);
    *(float4*)(g_xk + e) = ok;
    *(float4*)(g_xv + e) = ov;
    *(float4*)(g_xr + e) = orr;
}

// =====================================================================
// 2) fp32 SGEMM: C[M,N] = A[M,512] @ W[512,N], 128x128x8 tiles,
//    256 threads, 8x8 microtile, register prefetch.
//    asel/csel pick the static scratch buffers (avoids symbol-address APIs).
// =====================================================================
__global__ void __launch_bounds__(256, 2)
sgemm128(int asel, const float* __restrict__ Wt, int csel, float* __restrict__ Cext) {
    const int K = Csz, N = Csz;
    const float* A = (asel == 0) ? g_xk : (asel == 1) ? g_xv : (asel == 2) ? g_xr : g_o2;
    float*       Cc = (csel == 0) ? g_k : (csel == 1) ? g_v : (csel == 2) ? g_r : Cext;

    __shared__ float As[8][132];   // padded: conflict-free transpose stores
    __shared__ float Bs[8][128];

    int tid = threadIdx.x;
    int rowBase = blockIdx.y * 128;
    int colBase = blockIdx.x * 128;

    int aRow = tid >> 1;           // 0..127
    int aCol = (tid & 1) * 4;      // 0 or 4
    int bRow = tid >> 5;           // 0..7
    int bCol = (tid & 31) * 4;     // 0..124

    const float* Aptr = A + (rowBase + aRow) * K + aCol;
    const float* Bptr = Wt + bRow * N + colBase + bCol;

    float4 af = *(const float4*)Aptr;
    float4 bf = *(const float4*)Bptr;

    float acc[8][8];
    #pragma unroll
    for (int i = 0; i < 8; i++)
        #pragma unroll
        for (int j = 0; j < 8; j++) acc[i][j] = 0.f;

    int tx = tid & 15;             // 0..15 -> col group
    int ty = tid >> 4;             // 0..15 -> row group

    for (int k0 = 0; k0 < K; k0 += 8) {
        As[aCol + 0][aRow] = af.x;
        As[aCol + 1][aRow] = af.y;
        As[aCol + 2][aRow] = af.z;
        As[aCol + 3][aRow] = af.w;
        *(float4*)&Bs[bRow][bCol] = bf;
        __syncthreads();

        if (k0 + 8 < K) {
            af = *(const float4*)(Aptr + k0 + 8);
            bf = *(const float4*)(Bptr + (k0 + 8) * N);
        }

        #pragma unroll
        for (int kk = 0; kk < 8; kk++) {
            float4 a0 = *(float4*)&As[kk][ty * 8];
            float4 a1 = *(float4*)&As[kk][ty * 8 + 4];
            float4 b0 = *(float4*)&Bs[kk][tx * 8];
            float4 b1 = *(float4*)&Bs[kk][tx * 8 + 4];
            float ar[8] = {a0.x, a0.y, a0.z, a0.w, a1.x, a1.y, a1.z, a1.w};
            float br[8] = {b0.x, b0.y, b0.z, b0.w, b1.x, b1.y, b1.z, b1.w};
            #pragma unroll
            for (int i = 0; i < 8; i++)
                #pragma unroll
                for (int j = 0; j < 8; j++)
                    acc[i][j] += ar[i] * br[j];
        }
        __syncthreads();
    }

    #pragma unroll
    for (int i = 0; i < 8; i++) {
        int row = rowBase + ty * 8 + i;
        float4 o0 = make_float4(acc[i][0], acc[i][1], acc[i][2], acc[i][3]);
        float4 o1 = make_float4(acc[i][4], acc[i][5], acc[i][6], acc[i][7]);
        *(float4*)(Cc + row * N + colBase + tx * 8)     = o0;
        *(float4*)(Cc + row * N + colBase + tx * 8 + 4) = o1;
    }
}

// =====================================================================
// 3) WKV chunked scan.
// The recurrence tracks (p, q, o): true numerator a = p*e^o, denom b = q*e^o.
// a_t = e^w a_{t-1} + e^{k_t} v_t  -> associative log-sum-exp recurrence,
// so we do: per-chunk summaries, prefix combine, replay with prefix state.
// =====================================================================

// Pass 1: per-(lane, chunk) state summary starting from (0,0,-inf).
__global__ void wkv_pass1(const float* __restrict__ sd) {
    int tid = threadIdx.x;
    int bid = blockIdx.x;
    const int CB = Csz / 256;                       // 2
    int cblk = bid % CB;
    int j    = (bid / CB) % NCH;
    int b    = bid / (CB * NCH);
    int c    = cblk * 256 + tid;
    int lane = b * Csz + c;

    float w = sd[c] * (1.0f / Tsz);
    int base = (b * Tsz + j * LCH) * Csz + c;
    const float* kp = g_k + base;
    const float* vp = g_v + base;

    float p = 0.f, q = 0.f, o = NEG_INF;
    #pragma unroll 4
    for (int i = 0; i < LCH; i++) {
        float kt = kp[i * Csz];
        float vt = vp[i * Csz];
        float wo_ = w + o;
        float no = fmaxf(wo_, kt);
        float A  = __expf(wo_ - no);
        float Bv = __expf(kt - no);
        p = A * p + Bv * vt;
        q = A * q + Bv;
        o = no;
    }
    g_sp[j * BLsz + lane] = p;
    g_sq[j * BLsz + lane] = q;
    g_so[j * BLsz + lane] = o;
}

// Pass 1.5: sequential combine over the 32 chunks -> prefix states.
__global__ void wkv_combine(const float* __restrict__ sd) {
    int lane = blockIdx.x * blockDim.x + threadIdx.x;   // 0..4095
    int c = lane & (Csz - 1);
    float w  = sd[c] * (1.0f / Tsz);
    float wl = w * (float)LCH;                          // decay over one chunk
    float p = 0.f, q = 0.f, o = NEG_INF;
    for (int j = 0; j < NCH; j++) {
        g_pp[j * BLsz + lane] = p;
        g_pq[j * BLsz + lane] = q;
        g_po[j * BLsz + lane] = o;
        float pc = g_sp[j * BLsz + lane];
        float qc = g_sq[j * BLsz + lane];
        float oc = g_so[j * BLsz + lane];
        float od = o + wl;
        float m  = fmaxf(od, oc);
        float e1 = __expf(od - m);
        float e2 = __expf(oc - m);
        p = e1 * p + e2 * pc;
        q = e1 * q + e2 * qc;
        o = m;
    }
}

// Pass 2: replay each chunk from its prefix state, emit sigmoid(r)*y.
__global__ void wkv_pass2(const float* __restrict__ sd, const float* __restrict__ sf) {
    int tid = threadIdx.x;
    int bid = blockIdx.x;
    const int CB = Csz / 256;
    int cblk = bid % CB;
    int j    = (bid / CB) % NCH;
    int b    = bid / (CB * NCH);
    int c    = cblk * 256 + tid;
    int lane = b * Csz + c;

    float w = sd[c] * (1.0f / Tsz);
    float u = sf[c] * (1.0f / Tsz);

    float p = g_pp[j * BLsz + lane];
    float q = g_pq[j * BLsz + lane];
    float o = g_po[j * BLsz + lane];

    int base = (b * Tsz + j * LCH) * Csz + c;
    const float* kp = g_k  + base;
    const float* vp = g_v  + base;
    const float* rp = g_r  + base;
    float*       op = g_o2 + base;

    #pragma unroll 2
    for (int i = 0; i < LCH; i++) {
        float kt = kp[i * Csz];
        float vt = vp[i * Csz];
        float rt = rp[i * Csz];
        // output (u-boosted current token)
        float uk = u + kt;
        float no = fmaxf(o, uk);
        float A  = __expf(o - no);
        float Bt = __expf(uk - no);
        float y  = __fdividef(A * p + Bt * vt, A * q + Bt);
        float sr = __fdividef(1.0f, 1.0f + __expf(-rt));
        op[i * Csz] = sr * y;
        // state update
        float wo_ = w + o;
        float no2 = fmaxf(wo_, kt);
        float A2  = __expf(wo_ - no2);
        float B2  = __expf(kt - no2);
        p = A2 * p + B2 * vt;
        q = A2 * q + B2;
        o = no2;
    }
}

// =====================================================================
// launch
// =====================================================================
extern "C" void kernel_launch(void* const* d_in, const int* in_sizes, int n_in,
                              void* d_out, int out_size) {
    const float* x  = (const float*)d_in[0];
    const float* sd = (const float*)d_in[1];   // spatial_decay [C]
    const float* sf = (const float*)d_in[2];   // spatial_first [C]
    const float* mk = (const float*)d_in[3];
    const float* mv = (const float*)d_in[4];
    const float* mr = (const float*)d_in[5];
    const float* wk = (const float*)d_in[6];
    const float* wv = (const float*)d_in[7];
    const float* wr = (const float*)d_in[8];
    const float* wo = (const float*)d_in[9];
    float* out = (float*)d_out;

    dim3 gemm_grid(Csz / 128, Msz / 128);      // (4, 256)

    mix_kernel<<<(Msz * Csz / 4 + 255) / 256, 256>>>(x, mk, mv, mr);

    sgemm128<<<gemm_grid, 256>>>(0, wk, 0, nullptr);   // k = xk @ wk
    sgemm128<<<gemm_grid, 256>>>(1, wv, 1, nullptr);   // v = xv @ wv
    sgemm128<<<gemm_grid, 256>>>(2, wr, 2, nullptr);   // r = xr @ wr

    wkv_pass1 <<<Bsz * NCH * (Csz / 256), 256>>>(sd);
    wkv_combine<<<BLsz / 256, 256>>>(sd);
    wkv_pass2 <<<Bsz * NCH * (Csz / 256), 256>>>(sd, sf);

    sgemm128<<<gemm_grid, 256>>>(3, wo, 3, out);       // out = (sr*y) @ wo
}

// round 3
// speedup vs baseline: 1.7173x; 1.7173x over previous
#include <cuda_runtime.h>
#include <cuda_bf16.h>
#include <stdint.h>

#define Bsz 8
#define Tsz 4096
#define Csz 512
#define Msz (Bsz*Tsz)          // 32768 rows
#define BLsz (Bsz*Csz)         // 4096 scan lanes
#define NCH 32
#define LCH (Tsz/NCH)          // 128
#define NEG_INF -1e38f

// ---------------- static device scratch ----------------
__device__ __nv_bfloat16 g_xkhi[Msz*Csz], g_xklo[Msz*Csz];
__device__ __nv_bfloat16 g_xvhi[Msz*Csz], g_xvlo[Msz*Csz];
__device__ __nv_bfloat16 g_xrhi[Msz*Csz], g_xrlo[Msz*Csz];
__device__ __nv_bfloat16 g_yhi [Msz*Csz], g_ylo [Msz*Csz];
__device__ float g_k[Msz*Csz], g_v[Msz*Csz], g_r[Msz*Csz];
__device__ __nv_bfloat16 g_wthi[4][Csz*Csz], g_wtlo[4][Csz*Csz];   // [N,K] transposed
__device__ float g_sp[NCH*BLsz], g_sq[NCH*BLsz], g_so[NCH*BLsz];
__device__ float g_pp[NCH*BLsz], g_pq[NCH*BLsz], g_po[NCH*BLsz];

static __device__ __forceinline__ uint32_t smem_u32(const void* p) {
    uint32_t a;
    asm("{ .reg .u64 t; cvta.to.shared.u64 t, %1; cvt.u32.u64 %0, t; }" : "=r"(a) : "l"(p));
    return a;
}

#define LDSM4(r0,r1,r2,r3,addr) \
    asm volatile("ldmatrix.sync.aligned.m8n8.x4.shared.b16 {%0,%1,%2,%3}, [%4];" \
        : "=r"(r0),"=r"(r1),"=r"(r2),"=r"(r3) : "r"(addr))

#define MMA16816(c,a0,a1,a2,a3,b0,b1) \
    asm volatile("mma.sync.aligned.m16n8k16.row.col.f32.bf16.bf16.f32 " \
        "{%0,%1,%2,%3}, {%4,%5,%6,%7}, {%8,%9}, {%0,%1,%2,%3};" \
        : "+f"((c)[0]),"+f"((c)[1]),"+f"((c)[2]),"+f"((c)[3]) \
        : "r"(a0),"r"(a1),"r"(a2),"r"(a3),"r"(b0),"r"(b1))

// ---------------- split helper ----------------
static __device__ __forceinline__ void split_store4(float4 v, __nv_bfloat16* hi, __nv_bfloat16* lo) {
    ushort4 h, l;
    __nv_bfloat16 b;
    b = __float2bfloat16(v.x); h.x = __bfloat16_as_ushort(b);
    l.x = __bfloat16_as_ushort(__float2bfloat16(v.x - __bfloat162float(b)));
    b = __float2bfloat16(v.y); h.y = __bfloat16_as_ushort(b);
    l.y = __bfloat16_as_ushort(__float2bfloat16(v.y - __bfloat162float(b)));
    b = __float2bfloat16(v.z); h.z = __bfloat16_as_ushort(b);
    l.z = __bfloat16_as_ushort(__float2bfloat16(v.z - __bfloat162float(b)));
    b = __float2bfloat16(v.w); h.w = __bfloat16_as_ushort(b);
    l.w = __bfloat16_as_ushort(__float2bfloat16(v.w - __bfloat162float(b)));
    *(ushort4*)hi = h;
    *(ushort4*)lo = l;
}

// =====================================================================
// 1) time-shift + mix -> split-bf16 activations
// =====================================================================
__global__ void mix_kernel(const float* __restrict__ x,
                           const float* __restrict__ mk,
                           const float* __restrict__ mv,
                           const float* __restrict__ mr) {
    long gid = (long)blockIdx.x * blockDim.x + threadIdx.x;
    long e = gid * 4;
    if (e >= (long)Msz * Csz) return;
    int  c = (int)(e & (Csz - 1));
    long m = e >> 9;
    int  t = (int)(m & (Tsz - 1));
    float4 xc = *(const float4*)(x + e);
    float4 xp = make_float4(0.f, 0.f, 0.f, 0.f);
    if (t > 0) xp = *(const float4*)(x + e - Csz);
    float4 k4 = *(const float4*)(mk + c);
    float4 v4 = *(const float4*)(mv + c);
    float4 r4 = *(const float4*)(mr + c);
    float4 ok, ov, orr;
    ok.x = xc.x*k4.x + xp.x*(1.f-k4.x);  ok.y = xc.y*k4.y + xp.y*(1.f-k4.y);
    ok.z = xc.z*k4.z + xp.z*(1.f-k4.z);  ok.w = xc.w*k4.w + xp.w*(1.f-k4.w);
    ov.x = xc.x*v4.x + xp.x*(1.f-v4.x);  ov.y = xc.y*v4.y + xp.y*(1.f-v4.y);
    ov.z = xc.z*v4.z + xp.z*(1.f-v4.z);  ov.w = xc.w*v4.w + xp.w*(1.f-v4.w);
    orr.x = xc.x*r4.x + xp.x*(1.f-r4.x); orr.y = xc.y*r4.y + xp.y*(1.f-r4.y);
    orr.z = xc.z*r4.z + xp.z*(1.f-r4.z); orr.w = xc.w*r4.w + xp.w*(1.f-r4.w);
    split_store4(ok,  g_xkhi + e, g_xklo + e);
    split_store4(ov,  g_xvhi + e, g_xvlo + e);
    split_store4(orr, g_xrhi + e, g_xrlo + e);
}

// =====================================================================
// 2) weight prep: transpose [K,N]->[N,K] + bf16 split (4 matrices)
// =====================================================================
__global__ void prep_w(const float* __restrict__ w0, const float* __restrict__ w1,
                       const float* __restrict__ w2, const float* __restrict__ w3) {
    int gid = blockIdx.x * blockDim.x + threadIdx.x;
    int m = gid >> 18;
    int n = (gid >> 9) & 511;
    int k = gid & 511;
    const float* W = (m == 0) ? w0 : (m == 1) ? w1 : (m == 2) ? w2 : w3;
    float x = W[k * Csz + n];
    __nv_bfloat16 hb = __float2bfloat16(x);
    g_wthi[m][n * Csz + k] = hb;
    g_wtlo[m][n * Csz + k] = __float2bfloat16(x - __bfloat162float(hb));
}

// =====================================================================
// 3) HMMA split-bf16 GEMM: C[M,512] = A@W, effective K = 3*512.
//    CTA 128x128, BK=32, 8 warps x (64x32 warp tile), mma.m16n8k16.
// =====================================================================
#define BM 128
#define BN 128
#define BK 32
#define PADS 40      // smem row stride in bf16 elems (80B, conflict-free ldmatrix)

__global__ void __launch_bounds__(256)
bgemm(int sel, float* __restrict__ Cext) {
    __shared__ __align__(16) __nv_bfloat16 As[BM * PADS];
    __shared__ __align__(16) __nv_bfloat16 Bs[BN * PADS];

    const __nv_bfloat16 *Ahi, *Alo, *Bhi, *Blo; float* C;
    switch (sel) {
      case 0:  Ahi = g_xkhi; Alo = g_xklo; Bhi = g_wthi[0]; Blo = g_wtlo[0]; C = g_k;  break;
      case 1:  Ahi = g_xvhi; Alo = g_xvlo; Bhi = g_wthi[1]; Blo = g_wtlo[1]; C = g_v;  break;
      case 2:  Ahi = g_xrhi; Alo = g_xrlo; Bhi = g_wthi[2]; Blo = g_wtlo[2]; C = g_r;  break;
      default: Ahi = g_yhi;  Alo = g_ylo;  Bhi = g_wthi[3]; Blo = g_wtlo[3]; C = Cext; break;
    }
    const __nv_bfloat16* APs[3] = {Ahi, Ahi, Alo};
    const __nv_bfloat16* BPs[3] = {Bhi, Blo, Bhi};

    int tid = threadIdx.x, lid = tid & 31, wid = tid >> 5;
    int wm = wid & 1, wn = wid >> 1;            // warp grid 2(M) x 4(N)
    int rowBase = blockIdx.y * BM, colBase = blockIdx.x * BN;

    // gmem->smem staging: 2 x 16B pieces per thread for each of A,B
    int p0 = tid, p1 = tid + 256;
    int r0 = p0 >> 2, c0 = p0 & 3;
    int r1 = p1 >> 2, c1 = p1 & 3;
    float4 ra0, ra1, rb0, rb1;

    float acc[4][4][4];
    #pragma unroll
    for (int i = 0; i < 4; i++)
        #pragma unroll
        for (int j = 0; j < 4; j++)
            #pragma unroll
            for (int e = 0; e < 4; e++) acc[i][j][e] = 0.f;

    uint32_t sA = smem_u32(As), sB = smem_u32(Bs);
    // A frag: rows wm*64+(lid&15), kcol-half (lid>>4)*8
    uint32_t aBase = sA + (uint32_t)((wm*64 + (lid & 15)) * (PADS*2) + (lid >> 4) * 16);
    // B frag: rows wn*32+(lid&7)+((lid>>4)<<3), kcol-half ((lid>>3)&1)*8
    uint32_t bBase = sB + (uint32_t)((wn*32 + (lid & 7) + ((lid >> 4) << 3)) * (PADS*2)
                                     + ((lid >> 3) & 1) * 16);

    auto ldg = [&](int chunk) {
        int pass = chunk >> 4;
        int k0   = (chunk & 15) << 5;
        const __nv_bfloat16* Ap = APs[pass];
        const __nv_bfloat16* Bp = BPs[pass];
        ra0 = *(const float4*)(Ap + (size_t)(rowBase + r0) * Csz + k0 + c0 * 8);
        ra1 = *(const float4*)(Ap + (size_t)(rowBase + r1) * Csz + k0 + c1 * 8);
        rb0 = *(const float4*)(Bp + (size_t)(colBase + r0) * Csz + k0 + c0 * 8);
        rb1 = *(const float4*)(Bp + (size_t)(colBase + r1) * Csz + k0 + c1 * 8);
    };
    auto sts = [&]() {
        *(float4*)(As + r0 * PADS + c0 * 8) = ra0;
        *(float4*)(As + r1 * PADS + c1 * 8) = ra1;
        *(float4*)(Bs + r0 * PADS + c0 * 8) = rb0;
        *(float4*)(Bs + r1 * PADS + c1 * 8) = rb1;
    };

    ldg(0);
    sts();
    __syncthreads();

    for (int ch = 0; ch < 48; ch++) {
        if (ch < 47) ldg(ch + 1);        // gmem latency overlaps the MMA work below

        #pragma unroll
        for (int kk2 = 0; kk2 < 2; kk2++) {
            uint32_t a[4][4], b0r[4], b1r[4];
            #pragma unroll
            for (int mi = 0; mi < 4; mi++)
                LDSM4(a[mi][0], a[mi][1], a[mi][2], a[mi][3],
                      aBase + mi * (16 * PADS * 2) + kk2 * 32);
            LDSM4(b0r[0], b0r[1], b0r[2], b0r[3], bBase + kk2 * 32);
            LDSM4(b1r[0], b1r[1], b1r[2], b1r[3], bBase + (16 * PADS * 2) + kk2 * 32);
            #pragma unroll
            for (int mi = 0; mi < 4; mi++) {
                MMA16816(acc[mi][0], a[mi][0], a[mi][1], a[mi][2], a[mi][3], b0r[0], b0r[1]);
                MMA16816(acc[mi][1], a[mi][0], a[mi][1], a[mi][2], a[mi][3], b0r[2], b0r[3]);
                MMA16816(acc[mi][2], a[mi][0], a[mi][1], a[mi][2], a[mi][3], b1r[0], b1r[1]);
                MMA16816(acc[mi][3], a[mi][0], a[mi][1], a[mi][2], a[mi][3], b1r[2], b1r[3]);
            }
        }
        __syncthreads();
        if (ch < 47) {
            sts();
            __syncthreads();
        }
    }

    // epilogue: acc -> gmem
    int lr = lid >> 2, lc = (lid & 3) * 2;
    #pragma unroll
    for (int mi = 0; mi < 4; mi++) {
        #pragma unroll
        for (int ni = 0; ni < 4; ni++) {
            int row = rowBase + wm * 64 + mi * 16 + lr;
            int col = colBase + wn * 32 + ni * 8 + lc;
            *(float2*)(C + (size_t)row * Csz + col)       = make_float2(acc[mi][ni][0], acc[mi][ni][1]);
            *(float2*)(C + (size_t)(row + 8) * Csz + col) = make_float2(acc[mi][ni][2], acc[mi][ni][3]);
        }
    }
}

// =====================================================================
// 4) WKV chunked scan
// =====================================================================
__global__ void wkv_pass1(const float* __restrict__ sd) {
    int tid = threadIdx.x;
    int bid = blockIdx.x;
    const int CB = Csz / 256;
    int cblk = bid % CB;
    int j    = (bid / CB) % NCH;
    int b    = bid / (CB * NCH);
    int c    = cblk * 256 + tid;
    int lane = b * Csz + c;

    float w = sd[c] * (1.0f / Tsz);
    size_t base = ((size_t)b * Tsz + (size_t)j * LCH) * Csz + c;
    const float* kp = g_k + base;
    const float* vp = g_v + base;

    float p = 0.f, q = 0.f, o = NEG_INF;
    #pragma unroll 4
    for (int i = 0; i < LCH; i++) {
        float kt = kp[i * Csz];
        float vt = vp[i * Csz];
        float wo_ = w + o;
        float no = fmaxf(wo_, kt);
        float A  = __expf(wo_ - no);
        float Bv = __expf(kt - no);
        p = A * p + Bv * vt;
        q = A * q + Bv;
        o = no;
    }
    g_sp[j * BLsz + lane] = p;
    g_sq[j * BLsz + lane] = q;
    g_so[j * BLsz + lane] = o;
}

__global__ void wkv_combine(const float* __restrict__ sd) {
    int lane = blockIdx.x * blockDim.x + threadIdx.x;
    int c = lane & (Csz - 1);
    float w  = sd[c] * (1.0f / Tsz);
    float wl = w * (float)LCH;
    float p = 0.f, q = 0.f, o = NEG_INF;
    for (int j = 0; j < NCH; j++) {
        g_pp[j * BLsz + lane] = p;
        g_pq[j * BLsz + lane] = q;
        g_po[j * BLsz + lane] = o;
        float pc = g_sp[j * BLsz + lane];
        float qc = g_sq[j * BLsz + lane];
        float oc = g_so[j * BLsz + lane];
        float od = o + wl;
        float m  = fmaxf(od, oc);
        float e1 = __expf(od - m);
        float e2 = __expf(oc - m);
        p = e1 * p + e2 * pc;
        q = e1 * q + e2 * qc;
        o = m;
    }
}

__global__ void wkv_pass2(const float* __restrict__ sd, const float* __restrict__ sf) {
    int tid = threadIdx.x;
    int bid = blockIdx.x;
    const int CB = Csz / 256;
    int cblk = bid % CB;
    int j    = (bid / CB) % NCH;
    int b    = bid / (CB * NCH);
    int c    = cblk * 256 + tid;
    int lane = b * Csz + c;

    float w = sd[c] * (1.0f / Tsz);
    float u = sf[c] * (1.0f / Tsz);

    float p = g_pp[j * BLsz + lane];
    float q = g_pq[j * BLsz + lane];
    float o = g_po[j * BLsz + lane];

    size_t base = ((size_t)b * Tsz + (size_t)j * LCH) * Csz + c;
    const float* kp = g_k + base;
    const float* vp = g_v + base;
    const float* rp = g_r + base;

    #pragma unroll 2
    for (int i = 0; i < LCH; i++) {
        float kt = kp[i * Csz];
        float vt = vp[i * Csz];
        float rt = rp[i * Csz];
        float uk = u + kt;
        float no = fmaxf(o, uk);
        float A  = __expf(o - no);
        float Bt = __expf(uk - no);
        float y  = __fdividef(A * p + Bt * vt, A * q + Bt);
        float sr = __fdividef(1.0f, 1.0f + __expf(-rt));
        float sy = sr * y;
        __nv_bfloat16 hb = __float2bfloat16(sy);
        g_yhi[base + (size_t)i * Csz] = hb;
        g_ylo[base + (size_t)i * Csz] = __float2bfloat16(sy - __bfloat162float(hb));
        float wo_ = w + o;
        float no2 = fmaxf(wo_, kt);
        float A2  = __expf(wo_ - no2);
        float B2  = __expf(kt - no2);
        p = A2 * p + B2 * vt;
        q = A2 * q + B2;
        o = no2;
    }
}

// =====================================================================
// launch
// =====================================================================
extern "C" void kernel_launch(void* const* d_in, const int* in_sizes, int n_in,
                              void* d_out, int out_size) {
    const float* x  = (const float*)d_in[0];
    const float* sd = (const float*)d_in[1];
    const float* sf = (const float*)d_in[2];
    const float* mk = (const float*)d_in[3];
    const float* mv = (const float*)d_in[4];
    const float* mr = (const float*)d_in[5];
    const float* wk = (const float*)d_in[6];
    const float* wv = (const float*)d_in[7];
    const float* wr = (const float*)d_in[8];
    const float* wo = (const float*)d_in[9];
    float* out = (float*)d_out;

    dim3 gemm_grid(Csz / BN, Msz / BM);   // (4, 256)

    prep_w<<<(4 * Csz * Csz) / 256, 256>>>(wk, wv, wr, wo);
    mix_kernel<<<(Msz * Csz / 4 + 255) / 256, 256>>>(x, mk, mv, mr);

    bgemm<<<gemm_grid, 256>>>(0, nullptr);   // k
    bgemm<<<gemm_grid, 256>>>(1, nullptr);   // v
    bgemm<<<gemm_grid, 256>>>(2, nullptr);   // r

    wkv_pass1 <<<Bsz * NCH * (Csz / 256), 256>>>(sd);
    wkv_combine<<<BLsz / 256, 256>>>(sd);
    wkv_pass2 <<<Bsz * NCH * (Csz / 256), 256>>>(sd, sf);

    bgemm<<<gemm_grid, 256>>>(3, out);       // out = (sr*y) @ wo
}

// round 4
// speedup vs baseline: 2.1104x; 1.2289x over previous
#include <cuda_runtime.h>
#include <cuda_bf16.h>
#include <stdint.h>

#define Bsz 8
#define Tsz 4096
#define Csz 512
#define Msz (Bsz*Tsz)          // 32768 rows
#define BLsz (Bsz*Csz)         // 4096 scan lanes
#define NCH 32
#define LCH (Tsz/NCH)          // 128
#define NEG_INF -1e38f

// ---------------- static device scratch ----------------
__device__ __nv_bfloat16 g_xkhi[Msz*Csz], g_xklo[Msz*Csz];
__device__ __nv_bfloat16 g_xvhi[Msz*Csz], g_xvlo[Msz*Csz];
__device__ __nv_bfloat16 g_xrhi[Msz*Csz], g_xrlo[Msz*Csz];
__device__ __nv_bfloat16 g_yhi [Msz*Csz], g_ylo [Msz*Csz];
__device__ float g_k[Msz*Csz], g_v[Msz*Csz], g_r[Msz*Csz];
__device__ __nv_bfloat16 g_wthi[4][Csz*Csz], g_wtlo[4][Csz*Csz];   // [N,K] transposed
__device__ float g_sp[NCH*BLsz], g_sq[NCH*BLsz], g_so[NCH*BLsz];
__device__ float g_pp[NCH*BLsz], g_pq[NCH*BLsz], g_po[NCH*BLsz];

static __device__ __forceinline__ uint32_t smem_u32(const void* p) {
    uint32_t a;
    asm("{ .reg .u64 t; cvta.to.shared.u64 t, %1; cvt.u32.u64 %0, t; }" : "=r"(a) : "l"(p));
    return a;
}

#define LDSM4(r0,r1,r2,r3,addr) \
    asm volatile("ldmatrix.sync.aligned.m8n8.x4.shared.b16 {%0,%1,%2,%3}, [%4];" \
        : "=r"(r0),"=r"(r1),"=r"(r2),"=r"(r3) : "r"(addr))

#define MMA16816(c,a0,a1,a2,a3,b0,b1) \
    asm volatile("mma.sync.aligned.m16n8k16.row.col.f32.bf16.bf16.f32 " \
        "{%0,%1,%2,%3}, {%4,%5,%6,%7}, {%8,%9}, {%0,%1,%2,%3};" \
        : "+f"((c)[0]),"+f"((c)[1]),"+f"((c)[2]),"+f"((c)[3]) \
        : "r"(a0),"r"(a1),"r"(a2),"r"(a3),"r"(b0),"r"(b1))

#define CP16(dst, src) \
    asm volatile("cp.async.ca.shared.global [%0], [%1], 16;" :: "r"(dst), "l"(src))
#define CPCOMMIT() asm volatile("cp.async.commit_group;" ::: "memory")
#define CPWAIT0()  asm volatile("cp.async.wait_group 0;" ::: "memory")

// ---------------- split helper ----------------
static __device__ __forceinline__ void split_store4(float4 v, __nv_bfloat16* hi, __nv_bfloat16* lo) {
    ushort4 h, l;
    __nv_bfloat16 b;
    b = __float2bfloat16(v.x); h.x = __bfloat16_as_ushort(b);
    l.x = __bfloat16_as_ushort(__float2bfloat16(v.x - __bfloat162float(b)));
    b = __float2bfloat16(v.y); h.y = __bfloat16_as_ushort(b);
    l.y = __bfloat16_as_ushort(__float2bfloat16(v.y - __bfloat162float(b)));
    b = __float2bfloat16(v.z); h.z = __bfloat16_as_ushort(b);
    l.z = __bfloat16_as_ushort(__float2bfloat16(v.z - __bfloat162float(b)));
    b = __float2bfloat16(v.w); h.w = __bfloat16_as_ushort(b);
    l.w = __bfloat16_as_ushort(__float2bfloat16(v.w - __bfloat162float(b)));
    *(ushort4*)hi = h;
    *(ushort4*)lo = l;
}

// =====================================================================
// 1) time-shift + mix -> split-bf16 activations
// =====================================================================
__global__ void mix_kernel(const float* __restrict__ x,
                           const float* __restrict__ mk,
                           const float* __restrict__ mv,
                           const float* __restrict__ mr) {
    long gid = (long)blockIdx.x * blockDim.x + threadIdx.x;
    long e = gid * 4;
    if (e >= (long)Msz * Csz) return;
    int  c = (int)(e & (Csz - 1));
    long m = e >> 9;
    int  t = (int)(m & (Tsz - 1));
    float4 xc = *(const float4*)(x + e);
    float4 xp = make_float4(0.f, 0.f, 0.f, 0.f);
    if (t > 0) xp = *(const float4*)(x + e - Csz);
    float4 k4 = *(const float4*)(mk + c);
    float4 v4 = *(const float4*)(mv + c);
    float4 r4 = *(const float4*)(mr + c);
    float4 ok, ov, orr;
    ok.x = xc.x*k4.x + xp.x*(1.f-k4.x);  ok.y = xc.y*k4.y + xp.y*(1.f-k4.y);
    ok.z = xc.z*k4.z + xp.z*(1.f-k4.z);  ok.w = xc.w*k4.w + xp.w*(1.f-k4.w);
    ov.x = xc.x*v4.x + xp.x*(1.f-v4.x);  ov.y = xc.y*v4.y + xp.y*(1.f-v4.y);
    ov.z = xc.z*v4.z + xp.z*(1.f-v4.z);  ov.w = xc.w*v4.w + xp.w*(1.f-v4.w);
    orr.x = xc.x*r4.x + xp.x*(1.f-r4.x); orr.y = xc.y*r4.y + xp.y*(1.f-r4.y);
    orr.z = xc.z*r4.z + xp.z*(1.f-r4.z); orr.w = xc.w*r4.w + xp.w*(1.f-r4.w);
    split_store4(ok,  g_xkhi + e, g_xklo + e);
    split_store4(ov,  g_xvhi + e, g_xvlo + e);
    split_store4(orr, g_xrhi + e, g_xrlo + e);
}

// =====================================================================
// 2) weight prep: transpose [K,N]->[N,K] + bf16 split (4 matrices)
// =====================================================================
__global__ void prep_w(const float* __restrict__ w0, const float* __restrict__ w1,
                       const float* __restrict__ w2, const float* __restrict__ w3) {
    int gid = blockIdx.x * blockDim.x + threadIdx.x;
    int m = gid >> 18;
    int n = (gid >> 9) & 511;
    int k = gid & 511;
    const float* W = (m == 0) ? w0 : (m == 1) ? w1 : (m == 2) ? w2 : w3;
    float x = W[k * Csz + n];
    __nv_bfloat16 hb = __float2bfloat16(x);
    g_wthi[m][n * Csz + k] = hb;
    g_wtlo[m][n * Csz + k] = __float2bfloat16(x - __bfloat162float(hb));
}

// =====================================================================
// 3) fused split-bf16 HMMA GEMM.
//    Per k0 (K=32 slab): load Ahi/Alo/Bhi/Blo tiles once (cp.async,
//    2-stage ring), issue Ahi*Bhi + Ahi*Blo + Alo*Bhi into one fp32 acc.
//    CTA 128x128, 8 warps (2M x 4N), warp tile 64x32, one sync/iter.
// =====================================================================
#define BM 128
#define BN 128
#define PADS 40                       // 80B smem row stride (16B aligned, conflict-free)
#define BUFB (BM * PADS * 2)          // 10240 bytes per tile buffer
#define STGB (4 * BUFB)               // 40960 bytes per stage
#define DYNSM (2 * STGB)              // 81920 bytes

extern __shared__ char dynsm[];

__global__ void __launch_bounds__(256)
bgemm_f(int four, float* __restrict__ Cext) {
    int sel = (four == 3) ? 3 : (int)blockIdx.z;

    const __nv_bfloat16 *Ahi, *Alo, *Bhi, *Blo; float* C;
    switch (sel) {
      case 0:  Ahi = g_xkhi; Alo = g_xklo; Bhi = g_wthi[0]; Blo = g_wtlo[0]; C = g_k;  break;
      case 1:  Ahi = g_xvhi; Alo = g_xvlo; Bhi = g_wthi[1]; Blo = g_wtlo[1]; C = g_v;  break;
      case 2:  Ahi = g_xrhi; Alo = g_xrlo; Bhi = g_wthi[2]; Blo = g_wtlo[2]; C = g_r;  break;
      default: Ahi = g_yhi;  Alo = g_ylo;  Bhi = g_wthi[3]; Blo = g_wtlo[3]; C = Cext; break;
    }

    int tid = threadIdx.x, lid = tid & 31, wid = tid >> 5;
    int wm = wid & 1, wn = wid >> 1;
    int rowBase = blockIdx.y * BM, colBase = blockIdx.x * BN;

    uint32_t smb = smem_u32(dynsm);

    // gmem->smem granule mapping: 512 x 16B granules per 128x32 tile, 2/thread
    int r0 = tid >> 2, c0 = tid & 3;
    int r1 = (tid + 256) >> 2, c1 = (tid + 256) & 3;
    uint32_t d0 = (uint32_t)(r0 * (PADS*2) + c0 * 16);
    uint32_t d1 = (uint32_t)(r1 * (PADS*2) + c1 * 16);
    size_t sa0 = (size_t)(rowBase + r0) * Csz + c0 * 8;
    size_t sa1 = (size_t)(rowBase + r1) * Csz + c1 * 8;
    size_t sb0 = (size_t)(colBase + r0) * Csz + c0 * 8;
    size_t sb1 = (size_t)(colBase + r1) * Csz + c1 * 8;

    auto issue = [&](int i) {
        int k0 = i << 5;
        uint32_t st = smb + (uint32_t)((i & 1) * STGB);
        CP16(st + d0,            Ahi + sa0 + k0);
        CP16(st + d1,            Ahi + sa1 + k0);
        CP16(st + BUFB + d0,     Alo + sa0 + k0);
        CP16(st + BUFB + d1,     Alo + sa1 + k0);
        CP16(st + 2*BUFB + d0,   Bhi + sb0 + k0);
        CP16(st + 2*BUFB + d1,   Bhi + sb1 + k0);
        CP16(st + 3*BUFB + d0,   Blo + sb0 + k0);
        CP16(st + 3*BUFB + d1,   Blo + sb1 + k0);
        CPCOMMIT();
    };

    float acc[4][4][4];
    #pragma unroll
    for (int i = 0; i < 4; i++)
        #pragma unroll
        for (int j = 0; j < 4; j++)
            #pragma unroll
            for (int e = 0; e < 4; e++) acc[i][j][e] = 0.f;

    // ldmatrix fragment offsets (within a tile buffer)
    uint32_t aOff = (uint32_t)((wm*64 + (lid & 15)) * (PADS*2) + (lid >> 4) * 16);
    uint32_t bOff = (uint32_t)((wn*32 + (lid & 7) + ((lid >> 4) << 3)) * (PADS*2)
                               + ((lid >> 3) & 1) * 16);

    issue(0);

    for (int it = 0; it < 16; it++) {
        CPWAIT0();
        __syncthreads();
        if (it < 15) issue(it + 1);

        uint32_t st = smb + (uint32_t)((it & 1) * STGB);
        #pragma unroll
        for (int kk2 = 0; kk2 < 2; kk2++) {
            uint32_t kb = kk2 * 32;
            uint32_t a[4][4], bh[8], bl[8];
            #pragma unroll
            for (int mi = 0; mi < 4; mi++)
                LDSM4(a[mi][0], a[mi][1], a[mi][2], a[mi][3],
                      st + aOff + mi * (16*PADS*2) + kb);
            LDSM4(bh[0], bh[1], bh[2], bh[3], st + 2*BUFB + bOff + kb);
            LDSM4(bh[4], bh[5], bh[6], bh[7], st + 2*BUFB + bOff + (16*PADS*2) + kb);
            LDSM4(bl[0], bl[1], bl[2], bl[3], st + 3*BUFB + bOff + kb);
            LDSM4(bl[4], bl[5], bl[6], bl[7], st + 3*BUFB + bOff + (16*PADS*2) + kb);

            #pragma unroll
            for (int mi = 0; mi < 4; mi++) {
                MMA16816(acc[mi][0], a[mi][0], a[mi][1], a[mi][2], a[mi][3], bh[0], bh[1]);
                MMA16816(acc[mi][1], a[mi][0], a[mi][1], a[mi][2], a[mi][3], bh[2], bh[3]);
                MMA16816(acc[mi][2], a[mi][0], a[mi][1], a[mi][2], a[mi][3], bh[4], bh[5]);
                MMA16816(acc[mi][3], a[mi][0], a[mi][1], a[mi][2], a[mi][3], bh[6], bh[7]);
            }
            #pragma unroll
            for (int mi = 0; mi < 4; mi++) {
                MMA16816(acc[mi][0], a[mi][0], a[mi][1], a[mi][2], a[mi][3], bl[0], bl[1]);
                MMA16816(acc[mi][1], a[mi][0], a[mi][1], a[mi][2], a[mi][3], bl[2], bl[3]);
                MMA16816(acc[mi][2], a[mi][0], a[mi][1], a[mi][2], a[mi][3], bl[4], bl[5]);
                MMA16816(acc[mi][3], a[mi][0], a[mi][1], a[mi][2], a[mi][3], bl[6], bl[7]);
            }
            // reload A with lo-part, reuse bh
            #pragma unroll
            for (int mi = 0; mi < 4; mi++)
                LDSM4(a[mi][0], a[mi][1], a[mi][2], a[mi][3],
                      st + BUFB + aOff + mi * (16*PADS*2) + kb);
            #pragma unroll
            for (int mi = 0; mi < 4; mi++) {
                MMA16816(acc[mi][0], a[mi][0], a[mi][1], a[mi][2], a[mi][3], bh[0], bh[1]);
                MMA16816(acc[mi][1], a[mi][0], a[mi][1], a[mi][2], a[mi][3], bh[2], bh[3]);
                MMA16816(acc[mi][2], a[mi][0], a[mi][1], a[mi][2], a[mi][3], bh[4], bh[5]);
                MMA16816(acc[mi][3], a[mi][0], a[mi][1], a[mi][2], a[mi][3], bh[6], bh[7]);
            }
        }
        __syncthreads();   // all warps done reading stage (it&1) before it's refilled at it+2
    }

    // epilogue
    int lr = lid >> 2, lc = (lid & 3) * 2;
    #pragma unroll
    for (int mi = 0; mi < 4; mi++) {
        #pragma unroll
        for (int ni = 0; ni < 4; ni++) {
            int row = rowBase + wm * 64 + mi * 16 + lr;
            int col = colBase + wn * 32 + ni * 8 + lc;
            *(float2*)(C + (size_t)row * Csz + col)       = make_float2(acc[mi][ni][0], acc[mi][ni][1]);
            *(float2*)(C + (size_t)(row + 8) * Csz + col) = make_float2(acc[mi][ni][2], acc[mi][ni][3]);
        }
    }
}

// =====================================================================
// 4) WKV chunked scan
// =====================================================================
__global__ void wkv_pass1(const float* __restrict__ sd) {
    int tid = threadIdx.x;
    int bid = blockIdx.x;
    const int CB = Csz / 256;
    int cblk = bid % CB;
    int j    = (bid / CB) % NCH;
    int b    = bid / (CB * NCH);
    int c    = cblk * 256 + tid;
    int lane = b * Csz + c;

    float w = sd[c] * (1.0f / Tsz);
    size_t base = ((size_t)b * Tsz + (size_t)j * LCH) * Csz + c;
    const float* kp = g_k + base;
    const float* vp = g_v + base;

    float p = 0.f, q = 0.f, o = NEG_INF;
    #pragma unroll 4
    for (int i = 0; i < LCH; i++) {
        float kt = kp[i * Csz];
        float vt = vp[i * Csz];
        float wo_ = w + o;
        float no = fmaxf(wo_, kt);
        float A  = __expf(wo_ - no);
        float Bv = __expf(kt - no);
        p = A * p + Bv * vt;
        q = A * q + Bv;
        o = no;
    }
    g_sp[j * BLsz + lane] = p;
    g_sq[j * BLsz + lane] = q;
    g_so[j * BLsz + lane] = o;
}

__global__ void wkv_combine(const float* __restrict__ sd) {
    int lane = blockIdx.x * blockDim.x + threadIdx.x;
    int c = lane & (Csz - 1);
    float w  = sd[c] * (1.0f / Tsz);
    float wl = w * (float)LCH;
    float p = 0.f, q = 0.f, o = NEG_INF;
    for (int j = 0; j < NCH; j++) {
        g_pp[j * BLsz + lane] = p;
        g_pq[j * BLsz + lane] = q;
        g_po[j * BLsz + lane] = o;
        float pc = g_sp[j * BLsz + lane];
        float qc = g_sq[j * BLsz + lane];
        float oc = g_so[j * BLsz + lane];
        float od = o + wl;
        float m  = fmaxf(od, oc);
        float e1 = __expf(od - m);
        float e2 = __expf(oc - m);
        p = e1 * p + e2 * pc;
        q = e1 * q + e2 * qc;
        o = m;
    }
}

__global__ void wkv_pass2(const float* __restrict__ sd, const float* __restrict__ sf) {
    int tid = threadIdx.x;
    int bid = blockIdx.x;
    const int CB = Csz / 256;
    int cblk = bid % CB;
    int j    = (bid / CB) % NCH;
    int b    = bid / (CB * NCH);
    int c    = cblk * 256 + tid;
    int lane = b * Csz + c;

    float w = sd[c] * (1.0f / Tsz);
    float u = sf[c] * (1.0f / Tsz);

    float p = g_pp[j * BLsz + lane];
    float q = g_pq[j * BLsz + lane];
    float o = g_po[j * BLsz + lane];

    size_t base = ((size_t)b * Tsz + (size_t)j * LCH) * Csz + c;
    const float* kp = g_k + base;
    const float* vp = g_v + base;
    const float* rp = g_r + base;

    #pragma unroll 2
    for (int i = 0; i < LCH; i++) {
        float kt = kp[i * Csz];
        float vt = vp[i * Csz];
        float rt = rp[i * Csz];
        float uk = u + kt;
        float no = fmaxf(o, uk);
        float A  = __expf(o - no);
        float Bt = __expf(uk - no);
        float y  = __fdividef(A * p + Bt * vt, A * q + Bt);
        float sr = __fdividef(1.0f, 1.0f + __expf(-rt));
        float sy = sr * y;
        __nv_bfloat16 hb = __float2bfloat16(sy);
        g_yhi[base + (size_t)i * Csz] = hb;
        g_ylo[base + (size_t)i * Csz] = __float2bfloat16(sy - __bfloat162float(hb));
        float wo_ = w + o;
        float no2 = fmaxf(wo_, kt);
        float A2  = __expf(wo_ - no2);
        float B2  = __expf(kt - no2);
        p = A2 * p + B2 * vt;
        q = A2 * q + B2;
        o = no2;
    }
}

// =====================================================================
// launch
// =====================================================================
extern "C" void kernel_launch(void* const* d_in, const int* in_sizes, int n_in,
                              void* d_out, int out_size) {
    const float* x  = (const float*)d_in[0];
    const float* sd = (const float*)d_in[1];
    const float* sf = (const float*)d_in[2];
    const float* mk = (const float*)d_in[3];
    const float* mv = (const float*)d_in[4];
    const float* mr = (const float*)d_in[5];
    const float* wk = (const float*)d_in[6];
    const float* wv = (const float*)d_in[7];
    const float* wr = (const float*)d_in[8];
    const float* wo = (const float*)d_in[9];
    float* out = (float*)d_out;

    static int smem_set = 0;
    if (!smem_set) {
        cudaFuncSetAttribute(bgemm_f, cudaFuncAttributeMaxDynamicSharedMemorySize, DYNSM);
        smem_set = 1;
    }

    dim3 grid3(Csz / BN, Msz / BM, 3);   // (4, 256, 3)
    dim3 grid1(Csz / BN, Msz / BM, 1);

    prep_w<<<(4 * Csz * Csz) / 256, 256>>>(wk, wv, wr, wo);
    mix_kernel<<<(Msz * Csz / 4 + 255) / 256, 256>>>(x, mk, mv, mr);

    bgemm_f<<<grid3, 256, DYNSM>>>(0, nullptr);   // k, v, r

    wkv_pass1 <<<Bsz * NCH * (Csz / 256), 256>>>(sd);
    wkv_combine<<<BLsz / 256, 256>>>(sd);
    wkv_pass2 <<<Bsz * NCH * (Csz / 256), 256>>>(sd, sf);

    bgemm_f<<<grid1, 256, DYNSM>>>(3, out);       // out = (sr*y) @ wo
}